// round 4
// baseline (speedup 1.0000x reference)
#include <cuda_runtime.h>

#define NBINS 32
#define NDIM 64
#define NCELL 64
#define RMIN (-5.0f)
#define CELL_SCALE 6.4f           /* NCELL / 10 */
#define THREADS 512
#define BLOCKS 444                /* 148 SMs x 3 CTAs: one persistent wave */
#define STRIDE (BLOCKS * THREADS) /* 227328, compile-time */
#define UNROLL 4

/* smem layout (all [row][dim]: consecutive lanes = consecutive dims = no
   bank conflicts regardless of divergent row index):
   rec4 [NBINS][NDIM] float4 (R2,R1,R0,D2)   32768 B
   rec2 [NBINS][NDIM] float2 (D1,D0)         16384 B
   cell [NCELL][NDIM] float  (bnd|j packed)  16384 B
   kxf  [NBINS+1][NDIM] float                 8448 B   -> 73984 B, 3 CTAs/SM */
#define OFF_REC2 32768
#define OFF_CELL (32768 + 16384)
#define OFF_KXF  (32768 + 16384 + 16384)
#define SMEM_BYTES (OFF_KXF + 8448)

__global__ __launch_bounds__(THREADS, 3) void rqspline_kernel(
    const float* __restrict__ x,
    const float* __restrict__ bw,
    const float* __restrict__ bh,
    const float* __restrict__ ks,
    float* __restrict__ out,
    int total)
{
    extern __shared__ __align__(16) char smem[];
    float4* rec4 = (float4*)smem;
    float2* rec2 = (float2*)(smem + OFF_REC2);
    float*  cell = (float*) (smem + OFF_CELL);
    float*  kxf  = (float*) (smem + OFF_KXF);

    const int t = threadIdx.x;

    /* ---- phase 1: per-dim monomial coefficients (64 threads, double math) */
    if (t < NDIM) {
        float cx = RMIN, cy = RMIN;
        #pragma unroll
        for (int j = 0; j < NBINS; ++j) {
            const float w_in = bw[t * NBINS + j];
            const float h_in = bh[t * NBINS + j];
            const float nx = cx + w_in;   /* same fp32 cumsum as reference */
            const float ny = cy + h_in;
            const float wf = nx - cx;
            const float hf = ny - cy;
            const double dk  = (j == 0) ? 1.0 : (double)ks[t * (NBINS - 1) + j - 1];
            const double dk1 = (j == NBINS - 1) ? 1.0 : (double)ks[t * (NBINS - 1) + j];

            const double a = 1.0 / (double)wf;
            const double b = -a * (double)cx;       /* t = a*x + b */
            const double s = (double)hf * a;
            const double c = dk + dk1 - 2.0 * s;
            const double aa = a * a;
            const double tt2 = -aa, tt1 = a * (1.0 - 2.0 * b), tt0 = b * (1.0 - b);
            const double q2 = aa,  q1 = 2.0 * a * b,           q0 = b * b;
            const double D2 = c * tt2, D1 = c * tt1, D0 = s + c * tt0;
            const double hd = (double)hf;
            const double N2 = hd * (s * q2 + dk * tt2);
            const double N1 = hd * (s * q1 + dk * tt1);
            const double N0 = hd * (s * q0 + dk * tt0);
            const double yk = (double)cy;
            rec4[j * NDIM + t] = make_float4((float)(N2 + yk * D2),
                                             (float)(N1 + yk * D1),
                                             (float)(N0 + yk * D0),
                                             (float)D2);
            rec2[j * NDIM + t] = make_float2((float)D1, (float)D0);
            kxf[j * NDIM + t] = cx;
            cx = nx; cy = ny;
        }
        kxf[NBINS * NDIM + t] = cx;
    }
    __syncthreads();

    /* ---- phase 2: cell table, boundary float with j packed in low 5 bits */
    for (int e = t; e < NCELL * NDIM; e += THREADS) {
        const int c = e >> 6, d = e & (NDIM - 1);
        const float cs = RMIN + (float)c * (10.0f / NCELL);
        int j = min(c >> 1, NBINS - 1);
        while (j > 0 && kxf[j * NDIM + d] > cs) --j;
        while (j < NBINS - 1 && kxf[(j + 1) * NDIM + d] <= cs) ++j;
        int bits = __float_as_int(kxf[(j + 1) * NDIM + d]);
        bits = (bits & ~31) | j;   /* ~2e-5 boundary shift: harmless, spline is
                                      continuous across knots */
        cell[c * NDIM + d] = __int_as_float(bits);
    }
    __syncthreads();

    /* ---- phase 3: streaming eval, staged for memory-level parallelism ---- */
    const int tid = blockIdx.x * THREADS + t;
    const int d = tid & (NDIM - 1);      /* loop-invariant: STRIDE % 64 == 0 */
    const float4* rec4d = rec4 + d;
    const float2* rec2d = rec2 + d;
    const float*  celld = cell + d;
    const float hi = kxf[NBINS * NDIM + d];

    int i = tid;
    for (; i + (UNROLL - 1) * STRIDE < total; i += UNROLL * STRIDE) {
        float xv[UNROLL];
        #pragma unroll
        for (int u = 0; u < UNROLL; ++u)
            xv[u] = __ldg(x + i + u * STRIDE);

        int jj[UNROLL];
        #pragma unroll
        for (int u = 0; u < UNROLL; ++u) {
            int c = __float2int_rd(fmaf(xv[u], CELL_SCALE, -RMIN * CELL_SCALE));
            c = min(max(c, 0), NCELL - 1);
            const int b = __float_as_int(celld[c * NDIM]);
            int j = b & 31;
            if (xv[u] >= __int_as_float(b)) ++j;
            jj[u] = min(j, NBINS - 1);
        }

        float4 r4[UNROLL];
        float2 r2[UNROLL];
        #pragma unroll
        for (int u = 0; u < UNROLL; ++u) {
            r4[u] = rec4d[jj[u] * NDIM];
            r2[u] = rec2d[jj[u] * NDIM];
        }

        #pragma unroll
        for (int u = 0; u < UNROLL; ++u) {
            const float v = xv[u];
            const float num = fmaf(fmaf(r4[u].x, v, r4[u].y), v, r4[u].z);
            const float den = fmaf(fmaf(r4[u].w, v, r2[u].x), v, r2[u].y);
            const float y = __fdividef(num, den);
            out[i + u * STRIDE] = (v >= RMIN && v <= hi) ? y : v;
        }
    }
    for (; i < total; i += STRIDE) {
        const float v = __ldg(x + i);
        int c = __float2int_rd(fmaf(v, CELL_SCALE, -RMIN * CELL_SCALE));
        c = min(max(c, 0), NCELL - 1);
        const int b = __float_as_int(celld[c * NDIM]);
        int j = (b & 31) + ((v >= __int_as_float(b)) ? 1 : 0);
        j = min(j, NBINS - 1);
        const float4 r4 = rec4d[j * NDIM];
        const float2 r2 = rec2d[j * NDIM];
        const float num = fmaf(fmaf(r4.x, v, r4.y), v, r4.z);
        const float den = fmaf(fmaf(r4.w, v, r2.x), v, r2.y);
        const float y = __fdividef(num, den);
        out[i] = (v >= RMIN && v <= hi) ? y : v;
    }
}

extern "C" void kernel_launch(void* const* d_in, const int* in_sizes, int n_in,
                              void* d_out, int out_size) {
    const float* x  = (const float*)d_in[0];
    const float* bw = (const float*)d_in[1];
    const float* bh = (const float*)d_in[2];
    const float* ks = (const float*)d_in[3];
    float* out = (float*)d_out;
    const int total = in_sizes[0];

    cudaFuncSetAttribute(rqspline_kernel,
                         cudaFuncAttributeMaxDynamicSharedMemorySize, SMEM_BYTES);
    rqspline_kernel<<<BLOCKS, THREADS, SMEM_BYTES>>>(x, bw, bh, ks, out, total);
}

// round 5
// speedup vs baseline: 1.8417x; 1.8417x over previous
#include <cuda_runtime.h>

#define NBINS 32
#define NDIM 64
#define NCELL 64
#define RMIN (-5.0f)
#define CELL_SCALE 6.4f           /* NCELL / 10 */
#define THREADS 512
#define BLOCKS 296                /* 148 SMs x 2 CTAs: one persistent wave */
#define STRIDE (BLOCKS * THREADS) /* 151552, compile-time */
#define U 8                       /* pipeline batch */

/* smem layout (all [row][dim]: consecutive lanes = consecutive dims = no
   bank conflicts regardless of divergent row index):
   rec4 [NBINS][NDIM] float4 (R2,R1,R0,D2)   32768 B
   rec2 [NBINS][NDIM] float2 (D1,D0)         16384 B
   cell [NCELL][NDIM] float  (bnd|j packed)  16384 B
   kxf  [NBINS+1][NDIM] float                 8448 B   -> 73984 B, 2 CTAs/SM */
#define OFF_REC2 32768
#define OFF_CELL (32768 + 16384)
#define OFF_KXF  (32768 + 16384 + 16384)
#define SMEM_BYTES (OFF_KXF + 8448)

__device__ __forceinline__ void eval_batch(
    const float* __restrict__ xv,
    const float* __restrict__ celld,
    const float4* __restrict__ rec4d,
    const float2* __restrict__ rec2d,
    float hi, float* __restrict__ out, int i)
{
    int jj[U];
    #pragma unroll
    for (int u = 0; u < U; ++u) {
        int c = __float2int_rd(fmaf(xv[u], CELL_SCALE, -RMIN * CELL_SCALE));
        c = min(max(c, 0), NCELL - 1);
        const int b = __float_as_int(celld[c * NDIM]);
        int j = (b & 31) + ((xv[u] >= __int_as_float(b)) ? 1 : 0);
        jj[u] = min(j, NBINS - 1);
    }
    #pragma unroll
    for (int u = 0; u < U; ++u) {
        const float4 r4 = rec4d[jj[u] * NDIM];
        const float2 r2 = rec2d[jj[u] * NDIM];
        const float v = xv[u];
        const float num = fmaf(fmaf(r4.x, v, r4.y), v, r4.z);
        const float den = fmaf(fmaf(r4.w, v, r2.x), v, r2.y);
        const float y = __fdividef(num, den);
        out[i + u * STRIDE] = (v >= RMIN && v <= hi) ? y : v;
    }
}

__global__ __launch_bounds__(THREADS, 2) void rqspline_kernel(
    const float* __restrict__ x,
    const float* __restrict__ bw,
    const float* __restrict__ bh,
    const float* __restrict__ ks,
    float* __restrict__ out,
    int total)
{
    extern __shared__ __align__(16) char smem[];
    float4* rec4 = (float4*)smem;
    float2* rec2 = (float2*)(smem + OFF_REC2);
    float*  cell = (float*) (smem + OFF_CELL);
    float*  kxf  = (float*) (smem + OFF_KXF);

    const int t = threadIdx.x;
    const int tid = blockIdx.x * THREADS + t;

    /* ---- prefetch batch 0 BEFORE the table build: LDGs in flight while
       the block builds tables / waits at the barrier ---- */
    float xc[U];
    const bool full0 = (tid + (U - 1) * STRIDE < total);
    if (full0) {
        #pragma unroll
        for (int u = 0; u < U; ++u) xc[u] = __ldg(x + tid + u * STRIDE);
    }

    /* ---- phase 1: per-dim monomial coefficients (fp32 throughout) ---- */
    if (t < NDIM) {
        float cx = RMIN, cy = RMIN;
        #pragma unroll
        for (int j = 0; j < NBINS; ++j) {
            const float nx = cx + bw[t * NBINS + j];  /* reference fp32 cumsum */
            const float ny = cy + bh[t * NBINS + j];
            const float wf = nx - cx;
            const float hf = ny - cy;
            const float dk  = (j == 0) ? 1.0f : ks[t * (NBINS - 1) + j - 1];
            const float dk1 = (j == NBINS - 1) ? 1.0f : ks[t * (NBINS - 1) + j];

            const float a = 1.0f / wf;
            const float b = -a * cx;                 /* t = a*x + b */
            const float s = hf * a;
            const float c = dk + dk1 - 2.0f * s;
            const float aa = a * a;
            const float tt2 = -aa, tt1 = a * (1.0f - 2.0f * b), tt0 = b * (1.0f - b);
            const float q2 = aa,  q1 = 2.0f * a * b,             q0 = b * b;
            const float D2 = c * tt2, D1 = c * tt1, D0 = fmaf(c, tt0, s);
            const float N2 = hf * fmaf(s, q2, dk * tt2);
            const float N1 = hf * fmaf(s, q1, dk * tt1);
            const float N0 = hf * fmaf(s, q0, dk * tt0);
            rec4[j * NDIM + t] = make_float4(fmaf(cy, D2, N2),
                                             fmaf(cy, D1, N1),
                                             fmaf(cy, D0, N0),
                                             D2);
            rec2[j * NDIM + t] = make_float2(D1, D0);
            kxf[j * NDIM + t] = cx;
            cx = nx; cy = ny;
        }
        kxf[NBINS * NDIM + t] = cx;
    }
    __syncthreads();

    /* ---- phase 2: cell table, boundary float with j packed in low 5 bits */
    for (int e = t; e < NCELL * NDIM; e += THREADS) {
        const int c = e >> 6, d = e & (NDIM - 1);
        const float cs = RMIN + (float)c * (10.0f / NCELL);
        int j = min(c >> 1, NBINS - 1);
        while (j > 0 && kxf[j * NDIM + d] > cs) --j;
        while (j < NBINS - 1 && kxf[(j + 1) * NDIM + d] <= cs) ++j;
        int bits = __float_as_int(kxf[(j + 1) * NDIM + d]);
        bits = (bits & ~31) | j;   /* ~2e-5 boundary shift: harmless, the
                                      spline is continuous across knots */
        cell[c * NDIM + d] = __int_as_float(bits);
    }
    __syncthreads();

    /* ---- phase 3: software-pipelined streaming eval ---- */
    const int d = tid & (NDIM - 1);      /* loop-invariant: STRIDE % 64 == 0 */
    const float4* rec4d = rec4 + d;
    const float2* rec2d = rec2 + d;
    const float*  celld = cell + d;
    const float hi = kxf[NBINS * NDIM + d];

    int i = tid;
    for (; i + (2 * U - 1) * STRIDE < total; i += U * STRIDE) {
        float xn[U];
        #pragma unroll
        for (int u = 0; u < U; ++u)          /* next batch: LDGs in flight */
            xn[u] = __ldg(x + i + (U + u) * STRIDE);
        eval_batch(xc, celld, rec4d, rec2d, hi, out, i);
        #pragma unroll
        for (int u = 0; u < U; ++u) xc[u] = xn[u];
    }
    if (full0 && i + (U - 1) * STRIDE < total) {
        eval_batch(xc, celld, rec4d, rec2d, hi, out, i);
        i += U * STRIDE;
    }
    for (; i < total; i += STRIDE) {
        const float v = __ldg(x + i);
        int c = __float2int_rd(fmaf(v, CELL_SCALE, -RMIN * CELL_SCALE));
        c = min(max(c, 0), NCELL - 1);
        const int b = __float_as_int(celld[c * NDIM]);
        int j = (b & 31) + ((v >= __int_as_float(b)) ? 1 : 0);
        j = min(j, NBINS - 1);
        const float4 r4 = rec4d[j * NDIM];
        const float2 r2 = rec2d[j * NDIM];
        const float num = fmaf(fmaf(r4.x, v, r4.y), v, r4.z);
        const float den = fmaf(fmaf(r4.w, v, r2.x), v, r2.y);
        const float y = __fdividef(num, den);
        out[i] = (v >= RMIN && v <= hi) ? y : v;
    }
}

extern "C" void kernel_launch(void* const* d_in, const int* in_sizes, int n_in,
                              void* d_out, int out_size) {
    const float* x  = (const float*)d_in[0];
    const float* bw = (const float*)d_in[1];
    const float* bh = (const float*)d_in[2];
    const float* ks = (const float*)d_in[3];
    float* out = (float*)d_out;
    const int total = in_sizes[0];

    cudaFuncSetAttribute(rqspline_kernel,
                         cudaFuncAttributeMaxDynamicSharedMemorySize, SMEM_BYTES);
    rqspline_kernel<<<BLOCKS, THREADS, SMEM_BYTES>>>(x, bw, bh, ks, out, total);
}